// round 14
// baseline (speedup 1.0000x reference)
#include <cuda_runtime.h>
#include <cuda_fp16.h>
#include <cstdint>

#define BATCH 64
#define N 1024
#define RBLKS 32            // row-blocks per batch (32 rows each)

// Scratch: row offsets R, col offsets C, per-CTA column partials, exp cache
__device__ float    g_R[BATCH * N];
__device__ float    g_C[BATCH * N];
__device__ __half   g_parth[BATCH * RBLKS * N];     // 4 MB half partials
__device__ __half   g_e[(size_t)BATCH * N * N];     // 128 MB: exp(s) in fp16
__device__ unsigned g_cnt[BATCH];                   // per-batch arrival counters
                                                    // (self-resetting -> replay-safe)

// ---------------------------------------------------------------------------
// Per-batch C update, executed by the LAST CTA of batch b in a pass.
// C_new[b][j] = log( sum_r part[r][j] )  (+ C_old[b][j] unless FIRST).
// Safe: all 32 CTAs of batch b read g_C[b] in their prologue BEFORE storing
// partials, so overwriting g_C here races with nothing in this pass.
// ---------------------------------------------------------------------------
template <bool FIRST>
__device__ __forceinline__ void batch_c_update(int b, int tid) {
    #pragma unroll
    for (int t = 0; t < 2; t++) {
        const int jh = tid + (t << 8);            // 0..511 half2 columns
        float sx = 0.f, sy = 0.f;
        #pragma unroll
        for (int r = 0; r < RBLKS; r++) {
            const __half2 v = *reinterpret_cast<const __half2*>(
                g_parth + ((size_t)(b * RBLKS + r)) * N + (jh << 1));
            const float2 f = __half22float2(v);
            sx += f.x; sy += f.y;
        }
        float2* c2 = reinterpret_cast<float2*>(&g_C[b * N + (jh << 1)]);
        if (FIRST) {
            *c2 = make_float2(logf(sx), logf(sy));
        } else {
            const float2 c = *c2;
            *c2 = make_float2(logf(sx) + c.x, logf(sy) + c.y);
        }
    }
}

// Arrival protocol: returns true in ALL threads of the last CTA of batch b.
__device__ __forceinline__ bool arrive_last(int b) {
    __shared__ unsigned lastflag;
    __threadfence();                 // publish this thread's partial stores
    __syncthreads();                 // all threads fenced
    if (threadIdx.x == 0)
        lastflag = (atomicAdd(&g_cnt[b], 1u) == RBLKS - 1) ? 1u : 0u;
    __syncthreads();
    if (lastflag) __threadfence();   // acquire: see all CTAs' partials
    return lastflag != 0;
}

// ---------------------------------------------------------------------------
// Pass 0 (iters 0+1): reads fp32 s ONCE, writes e = exp(s) as half,
// R[i] = log(sum_j exp(s_ij)), col partials, then last-CTA C update.
// Warp-per-row, 4 rows/warp. grid = (RBLKS, BATCH), block = 256.
// ---------------------------------------------------------------------------
__global__ void __launch_bounds__(256) pass0(const float* __restrict__ s) {
    __shared__ __half2 stage[8][N / 2];   // 16 KB
    const int b    = blockIdx.y;
    const int tid  = threadIdx.x;
    const int warp = tid >> 5;
    const int lane = tid & 31;

    __half2 cacc[16];
    #pragma unroll
    for (int k = 0; k < 16; k++) cacc[k] = __float2half2_rn(0.f);

    #pragma unroll 1
    for (int g = 0; g < 4; g++) {
        const int row = (blockIdx.x << 5) + (g << 3) + warp;
        const float*  p  = s   + ((size_t)b << 20) + ((size_t)row << 10);
        __half*       ep = g_e + ((size_t)b << 20) + ((size_t)row << 10);

        __half2 eh[16];
        float sum = 0.f;
        #pragma unroll
        for (int k = 0; k < 8; k++) {
            const int j = (lane << 2) + (k << 7);
            const float4 sv = __ldcs(reinterpret_cast<const float4*>(p + j));
            const float ex = __expf(sv.x), ey = __expf(sv.y);
            const float ez = __expf(sv.z), ew = __expf(sv.w);
            const __half2 h0 = __floats2half2_rn(ex, ey);
            const __half2 h1 = __floats2half2_rn(ez, ew);
            eh[2*k+0] = h0; eh[2*k+1] = h1;
            uint2 u;
            u.x = *reinterpret_cast<const unsigned int*>(&h0);
            u.y = *reinterpret_cast<const unsigned int*>(&h1);
            __stcs(reinterpret_cast<uint2*>(ep + j), u);
            sum += (ex + ey) + (ez + ew);
        }
        #pragma unroll
        for (int off = 16; off; off >>= 1)
            sum += __shfl_xor_sync(0xffffffffu, sum, off);

        if (lane == 0) g_R[b * N + row] = logf(sum);
        const __half2 rin = __float2half2_rn(__fdividef(1.f, sum));
        #pragma unroll
        for (int k = 0; k < 16; k++) cacc[k] = __hfma2(eh[k], rin, cacc[k]);
    }

    #pragma unroll
    for (int k = 0; k < 8; k++) {
        const int jh = (lane << 1) + (k << 6);
        stage[warp][jh]     = cacc[2*k+0];
        stage[warp][jh + 1] = cacc[2*k+1];
    }
    __syncthreads();
    float a0 = 0.f, a1 = 0.f, a2 = 0.f, a3 = 0.f;
    #pragma unroll
    for (int w = 0; w < 8; w++) {
        const float2 f0 = __half22float2(stage[w][(tid << 1)]);
        const float2 f1 = __half22float2(stage[w][(tid << 1) + 1]);
        a0 += f0.x; a1 += f0.y; a2 += f1.x; a3 += f1.y;
    }
    const __half2 h0 = __floats2half2_rn(a0, a1);
    const __half2 h1 = __floats2half2_rn(a2, a3);
    uint2 u;
    u.x = *reinterpret_cast<const unsigned int*>(&h0);
    u.y = *reinterpret_cast<const unsigned int*>(&h1);
    reinterpret_cast<uint2*>(
        g_parth + ((size_t)(b * RBLKS + blockIdx.x)) * N)[tid] = u;

    if (arrive_last(b)) {
        batch_c_update<true>(b, tid);
        __syncthreads();
        if (tid == 0) g_cnt[b] = 0;    // reset for next pass / next replay
    }
}

// ---------------------------------------------------------------------------
// Half pass (one iter pair), HALF2-NATIVE: reads the 128 MB exp-cache.
// exp(s - C) = e * w with w[j] = exp(-C[j]) computed fp32, STORED half2.
// Ends with last-CTA C update (no separate finalize kernel).
// grid = (RBLKS, BATCH), block = 256, warp-per-row, 4 rows/warp.
// ---------------------------------------------------------------------------
__global__ void __launch_bounds__(256) pass_h() {
    __shared__ __half2 w2_s[N / 2];       // 1 KB
    __shared__ __half2 stage[8][N / 2];   // 16 KB
    const int b    = blockIdx.y;
    const int tid  = threadIdx.x;
    const int warp = tid >> 5;
    const int lane = tid & 31;

    {   // prologue: w = exp(-C[b]) fp32 -> half2  (reads C BEFORE any partials)
        const float4 c = *reinterpret_cast<const float4*>(&g_C[b * N + (tid << 2)]);
        w2_s[(tid << 1)]     = __floats2half2_rn(__expf(-c.x), __expf(-c.y));
        w2_s[(tid << 1) + 1] = __floats2half2_rn(__expf(-c.z), __expf(-c.w));
    }
    __syncthreads();

    __half2 cacc[16];
    #pragma unroll
    for (int k = 0; k < 16; k++) cacc[k] = __float2half2_rn(0.f);

    #pragma unroll 1
    for (int g = 0; g < 4; g++) {
        const int row = (blockIdx.x << 5) + (g << 3) + warp;
        const __half2* ep2 = reinterpret_cast<const __half2*>(
            g_e + ((size_t)b << 20) + ((size_t)row << 10));

        __half2 ph[16];
        float sum = 0.f;
        #pragma unroll
        for (int k = 0; k < 4; k++) {
            const int jh = (lane << 2) + (k << 7);
            const uint4 u  = __ldcs(reinterpret_cast<const uint4*>(ep2 + jh));
            const uint4 wv = *reinterpret_cast<const uint4*>(&w2_s[jh]);
            const __half2 p0 = __hmul2(*reinterpret_cast<const __half2*>(&u.x),
                                       *reinterpret_cast<const __half2*>(&wv.x));
            const __half2 p1 = __hmul2(*reinterpret_cast<const __half2*>(&u.y),
                                       *reinterpret_cast<const __half2*>(&wv.y));
            const __half2 p2 = __hmul2(*reinterpret_cast<const __half2*>(&u.z),
                                       *reinterpret_cast<const __half2*>(&wv.z));
            const __half2 p3 = __hmul2(*reinterpret_cast<const __half2*>(&u.w),
                                       *reinterpret_cast<const __half2*>(&wv.w));
            ph[4*k+0] = p0; ph[4*k+1] = p1; ph[4*k+2] = p2; ph[4*k+3] = p3;
            const __half2 t = __hadd2(__hadd2(p0, p1), __hadd2(p2, p3));
            const float2 tf = __half22float2(t);
            sum += tf.x + tf.y;
        }
        #pragma unroll
        for (int off = 16; off; off >>= 1)
            sum += __shfl_xor_sync(0xffffffffu, sum, off);

        if (lane == 0) g_R[b * N + row] = logf(sum);   // last pass's R -> out
        const __half2 rin = __float2half2_rn(__fdividef(1.f, sum));
        #pragma unroll
        for (int k = 0; k < 16; k++) cacc[k] = __hfma2(ph[k], rin, cacc[k]);
    }

    #pragma unroll
    for (int k = 0; k < 4; k++) {
        const int jh = (lane << 2) + (k << 7);
        #pragma unroll
        for (int m = 0; m < 4; m++) stage[warp][jh + m] = cacc[4*k + m];
    }
    __syncthreads();
    float a0 = 0.f, a1 = 0.f, a2 = 0.f, a3 = 0.f;
    #pragma unroll
    for (int w = 0; w < 8; w++) {
        const float2 f0 = __half22float2(stage[w][(tid << 1)]);
        const float2 f1 = __half22float2(stage[w][(tid << 1) + 1]);
        a0 += f0.x; a1 += f0.y; a2 += f1.x; a3 += f1.y;
    }
    const __half2 h0 = __floats2half2_rn(a0, a1);
    const __half2 h1 = __floats2half2_rn(a2, a3);
    uint2 u;
    u.x = *reinterpret_cast<const unsigned int*>(&h0);
    u.y = *reinterpret_cast<const unsigned int*>(&h1);
    reinterpret_cast<uint2*>(
        g_parth + ((size_t)(b * RBLKS + blockIdx.x)) * N)[tid] = u;

    if (arrive_last(b)) {
        batch_c_update<false>(b, tid);
        __syncthreads();
        if (tid == 0) g_cnt[b] = 0;    // reset for next pass / next replay
    }
}

// ---------------------------------------------------------------------------
// Output pass: out = e_half * exp(-R[b][i] - C[b][j]).
// Reads the 128 MB half exp-cache. 8 elements per thread (one uint4).
// ---------------------------------------------------------------------------
__global__ void __launch_bounds__(256) out_pass(float4* __restrict__ o4) {
    const size_t gid  = (size_t)blockIdx.x * 256 + threadIdx.x;
    const size_t base = gid << 3;                    // element index (8/thread)
    const int b = (int)(base >> 20);
    const int i = (int)(base >> 10) & (N - 1);
    const int j = (int)base & (N - 1);

    const uint4 u = __ldcs(reinterpret_cast<const uint4*>(
        g_e + ((size_t)b << 20) + ((size_t)i << 10) + j));
    const float2 e0 = __half22float2(*reinterpret_cast<const __half2*>(&u.x));
    const float2 e1 = __half22float2(*reinterpret_cast<const __half2*>(&u.y));
    const float2 e2 = __half22float2(*reinterpret_cast<const __half2*>(&u.z));
    const float2 e3 = __half22float2(*reinterpret_cast<const __half2*>(&u.w));

    const float r = __ldg(&g_R[(b << 10) + i]);
    const float4 ca = *reinterpret_cast<const float4*>(&g_C[(b << 10) + j]);
    const float4 cb = *reinterpret_cast<const float4*>(&g_C[(b << 10) + j + 4]);

    float4 oa, ob;
    oa.x = e0.x * __expf(-r - ca.x);
    oa.y = e0.y * __expf(-r - ca.y);
    oa.z = e1.x * __expf(-r - ca.z);
    oa.w = e1.y * __expf(-r - ca.w);
    ob.x = e2.x * __expf(-r - cb.x);
    ob.y = e2.y * __expf(-r - cb.y);
    ob.z = e3.x * __expf(-r - cb.z);
    ob.w = e3.y * __expf(-r - cb.w);
    __stcs(o4 + (gid << 1), oa);
    __stcs(o4 + (gid << 1) + 1, ob);
}

// ---------------------------------------------------------------------------
extern "C" void kernel_launch(void* const* d_in, const int* in_sizes, int n_in,
                              void* d_out, int out_size) {
    const float* s = (const float*)d_in[0];
    float* out = (float*)d_out;

    const dim3 fgrid(RBLKS, BATCH);
    const int out_blocks = (BATCH * N * N / 8) / 256; // 8 elems per thread

    pass0<<<fgrid, 256>>>(s);    // iters 0+1 (+ C update by last CTA per batch)
    pass_h<<<fgrid, 256>>>();    // iters 2+3
    pass_h<<<fgrid, 256>>>();    // iters 4+5
    pass_h<<<fgrid, 256>>>();    // iters 6+7
    pass_h<<<fgrid, 256>>>();    // iters 8+9
    out_pass<<<out_blocks, 256>>>((float4*)out);
}

// round 15
// speedup vs baseline: 1.0155x; 1.0155x over previous
#include <cuda_runtime.h>
#include <cuda_fp16.h>
#include <cstdint>

#define BATCH 64
#define N 1024
#define RBLKS 32            // row-blocks per batch (32 rows each)

// Scratch: row offsets R, col offsets C, per-CTA column partials, exp cache
__device__ float  g_R[BATCH * N];
__device__ float  g_C[BATCH * N];
__device__ __half g_parth[BATCH * RBLKS * N];       // 4 MB half partials
__device__ __half g_e[(size_t)BATCH * N * N];       // 128 MB: exp(s) in fp16

// ---------------------------------------------------------------------------
// Pass 0 (iters 0+1): reads fp32 s ONCE, writes e = exp(s) as half for all
// later passes, computes R[i] = log(sum_j exp(s_ij)) and column partials
// part[j] += exp(s_ij)/sum_i. Warp-per-row, 4 rows/warp.
// grid = (RBLKS, BATCH), block = 256.
// ---------------------------------------------------------------------------
__global__ void __launch_bounds__(256) pass0(const float* __restrict__ s) {
    __shared__ __half2 stage[8][N / 2];   // 16 KB
    const int b    = blockIdx.y;
    const int tid  = threadIdx.x;
    const int warp = tid >> 5;
    const int lane = tid & 31;

    __half2 cacc[16];
    #pragma unroll
    for (int k = 0; k < 16; k++) cacc[k] = __float2half2_rn(0.f);

    #pragma unroll 1
    for (int g = 0; g < 4; g++) {
        const int row = (blockIdx.x << 5) + (g << 3) + warp;
        const float*  p  = s   + ((size_t)b << 20) + ((size_t)row << 10);
        __half*       ep = g_e + ((size_t)b << 20) + ((size_t)row << 10);

        __half2 eh[16];
        float sum = 0.f;
        #pragma unroll
        for (int k = 0; k < 8; k++) {
            const int j = (lane << 2) + (k << 7);
            const float4 sv = __ldcs(reinterpret_cast<const float4*>(p + j));
            const float ex = __expf(sv.x), ey = __expf(sv.y);
            const float ez = __expf(sv.z), ew = __expf(sv.w);
            const __half2 h0 = __floats2half2_rn(ex, ey);
            const __half2 h1 = __floats2half2_rn(ez, ew);
            eh[2*k+0] = h0; eh[2*k+1] = h1;
            uint2 u;
            u.x = *reinterpret_cast<const unsigned int*>(&h0);
            u.y = *reinterpret_cast<const unsigned int*>(&h1);
            __stcs(reinterpret_cast<uint2*>(ep + j), u);
            sum += (ex + ey) + (ez + ew);
        }
        #pragma unroll
        for (int off = 16; off; off >>= 1)
            sum += __shfl_xor_sync(0xffffffffu, sum, off);

        if (lane == 0) g_R[b * N + row] = logf(sum);
        const __half2 rin = __float2half2_rn(__fdividef(1.f, sum));
        #pragma unroll
        for (int k = 0; k < 16; k++) cacc[k] = __hfma2(eh[k], rin, cacc[k]);
    }

    #pragma unroll
    for (int k = 0; k < 8; k++) {
        const int jh = (lane << 1) + (k << 6);
        stage[warp][jh]     = cacc[2*k+0];
        stage[warp][jh + 1] = cacc[2*k+1];
    }
    __syncthreads();
    float a0 = 0.f, a1 = 0.f, a2 = 0.f, a3 = 0.f;
    #pragma unroll
    for (int w = 0; w < 8; w++) {
        const float2 f0 = __half22float2(stage[w][(tid << 1)]);
        const float2 f1 = __half22float2(stage[w][(tid << 1) + 1]);
        a0 += f0.x; a1 += f0.y; a2 += f1.x; a3 += f1.y;
    }
    const __half2 h0 = __floats2half2_rn(a0, a1);
    const __half2 h1 = __floats2half2_rn(a2, a3);
    uint2 u;
    u.x = *reinterpret_cast<const unsigned int*>(&h0);
    u.y = *reinterpret_cast<const unsigned int*>(&h1);
    reinterpret_cast<uint2*>(
        g_parth + ((size_t)(b * RBLKS + blockIdx.x)) * N)[tid] = u;
}

// ---------------------------------------------------------------------------
// Half pass (one iter pair), TWO ROWS PER ITERATION for MLP=8:
// both rows' 4x LDG.128 are issued back-to-back, then row A is processed
// (its tail covered by row B's in-flight loads), then row B.
// exp(s - C) = e * w with w[j] = exp(-C[j]) computed fp32, STORED half2.
// grid = (RBLKS, BATCH), block = 256, warp handles rows {base+warp, +8}.
// ---------------------------------------------------------------------------
__device__ __forceinline__ float row_products(const uint4* __restrict__ u,
                                              const __half2* __restrict__ w2_s,
                                              int lane, __half2* __restrict__ ph) {
    float sum = 0.f;
    #pragma unroll
    for (int k = 0; k < 4; k++) {
        const int jh = (lane << 2) + (k << 7);
        const uint4 wv = *reinterpret_cast<const uint4*>(&w2_s[jh]);
        const __half2 p0 = __hmul2(*reinterpret_cast<const __half2*>(&u[k].x),
                                   *reinterpret_cast<const __half2*>(&wv.x));
        const __half2 p1 = __hmul2(*reinterpret_cast<const __half2*>(&u[k].y),
                                   *reinterpret_cast<const __half2*>(&wv.y));
        const __half2 p2 = __hmul2(*reinterpret_cast<const __half2*>(&u[k].z),
                                   *reinterpret_cast<const __half2*>(&wv.z));
        const __half2 p3 = __hmul2(*reinterpret_cast<const __half2*>(&u[k].w),
                                   *reinterpret_cast<const __half2*>(&wv.w));
        ph[4*k+0] = p0; ph[4*k+1] = p1; ph[4*k+2] = p2; ph[4*k+3] = p3;
        const __half2 t = __hadd2(__hadd2(p0, p1), __hadd2(p2, p3));
        const float2 tf = __half22float2(t);
        sum += tf.x + tf.y;
    }
    return sum;
}

__global__ void __launch_bounds__(256) pass_h() {
    __shared__ __half2 w2_s[N / 2];       // 1 KB
    __shared__ __half2 stage[8][N / 2];   // 16 KB
    const int b    = blockIdx.y;
    const int tid  = threadIdx.x;
    const int warp = tid >> 5;
    const int lane = tid & 31;

    {   // prologue: w = exp(-C[b]) fp32 -> half2
        const float4 c = *reinterpret_cast<const float4*>(&g_C[b * N + (tid << 2)]);
        w2_s[(tid << 1)]     = __floats2half2_rn(__expf(-c.x), __expf(-c.y));
        w2_s[(tid << 1) + 1] = __floats2half2_rn(__expf(-c.z), __expf(-c.w));
    }
    __syncthreads();

    __half2 cacc[16];
    #pragma unroll
    for (int k = 0; k < 16; k++) cacc[k] = __float2half2_rn(0.f);

    #pragma unroll 1
    for (int g = 0; g < 2; g++) {
        const int rowA = (blockIdx.x << 5) + (g << 4) + warp;
        const int rowB = rowA + 8;
        const __half2* epA = reinterpret_cast<const __half2*>(
            g_e + ((size_t)b << 20) + ((size_t)rowA << 10));
        const __half2* epB = reinterpret_cast<const __half2*>(
            g_e + ((size_t)b << 20) + ((size_t)rowB << 10));

        // issue all 8 LDG.128 (both rows) before any math
        uint4 uA[4], uB[4];
        #pragma unroll
        for (int k = 0; k < 4; k++)
            uA[k] = __ldcs(reinterpret_cast<const uint4*>(epA + (lane << 2) + (k << 7)));
        #pragma unroll
        for (int k = 0; k < 4; k++)
            uB[k] = __ldcs(reinterpret_cast<const uint4*>(epB + (lane << 2) + (k << 7)));

        // ---- row A ----
        {
            __half2 ph[16];
            float sum = row_products(uA, w2_s, lane, ph);
            #pragma unroll
            for (int off = 16; off; off >>= 1)
                sum += __shfl_xor_sync(0xffffffffu, sum, off);
            if (lane == 0) g_R[b * N + rowA] = logf(sum);
            const __half2 rin = __float2half2_rn(__fdividef(1.f, sum));
            #pragma unroll
            for (int k = 0; k < 16; k++) cacc[k] = __hfma2(ph[k], rin, cacc[k]);
        }
        // ---- row B ----
        {
            __half2 ph[16];
            float sum = row_products(uB, w2_s, lane, ph);
            #pragma unroll
            for (int off = 16; off; off >>= 1)
                sum += __shfl_xor_sync(0xffffffffu, sum, off);
            if (lane == 0) g_R[b * N + rowB] = logf(sum);
            const __half2 rin = __float2half2_rn(__fdividef(1.f, sum));
            #pragma unroll
            for (int k = 0; k < 16; k++) cacc[k] = __hfma2(ph[k], rin, cacc[k]);
        }
    }

    // cross-warp reduce of column partials (cols j = 2*(lane*4+k*128)+m)
    #pragma unroll
    for (int k = 0; k < 4; k++) {
        const int jh = (lane << 2) + (k << 7);
        #pragma unroll
        for (int m = 0; m < 4; m++) stage[warp][jh + m] = cacc[4*k + m];
    }
    __syncthreads();
    float a0 = 0.f, a1 = 0.f, a2 = 0.f, a3 = 0.f;
    #pragma unroll
    for (int w = 0; w < 8; w++) {
        const float2 f0 = __half22float2(stage[w][(tid << 1)]);
        const float2 f1 = __half22float2(stage[w][(tid << 1) + 1]);
        a0 += f0.x; a1 += f0.y; a2 += f1.x; a3 += f1.y;
    }
    const __half2 h0 = __floats2half2_rn(a0, a1);
    const __half2 h1 = __floats2half2_rn(a2, a3);
    uint2 u;
    u.x = *reinterpret_cast<const unsigned int*>(&h0);
    u.y = *reinterpret_cast<const unsigned int*>(&h1);
    reinterpret_cast<uint2*>(
        g_parth + ((size_t)(b * RBLKS + blockIdx.x)) * N)[tid] = u;
}

// ---------------------------------------------------------------------------
// Finalize: C_new[b][j] = log( sum over RBLKS half partials ) + C_old.
// FIRST=true: the pass ran with C==0 -> write log(sum) directly (must NOT
// read g_C: stale from the previous graph replay). grid = 128 CTAs.
// ---------------------------------------------------------------------------
template <bool FIRST>
__global__ void __launch_bounds__(256) finalize_col() {
    const int q  = blockIdx.x * 256 + threadIdx.x;   // half2 index: b*512 + jh
    const int b  = q >> 9;
    const int jh = q & 511;
    float sx = 0.f, sy = 0.f;
    #pragma unroll
    for (int r = 0; r < RBLKS; r++) {
        const __half2 v = *reinterpret_cast<const __half2*>(
            g_parth + ((size_t)(b * RBLKS + r)) * N + (jh << 1));
        const float2 f = __half22float2(v);
        sx += f.x; sy += f.y;
    }
    float2* c2 = reinterpret_cast<float2*>(&g_C[b * N + (jh << 1)]);
    if (FIRST) {
        *c2 = make_float2(logf(sx), logf(sy));
    } else {
        const float2 c = *c2;
        *c2 = make_float2(logf(sx) + c.x, logf(sy) + c.y);
    }
}

// ---------------------------------------------------------------------------
// Output pass: out = e_half * exp(-R[b][i] - C[b][j]).
// Reads the 128 MB half exp-cache. 8 elements per thread (one uint4).
// ---------------------------------------------------------------------------
__global__ void __launch_bounds__(256) out_pass(float4* __restrict__ o4) {
    const size_t gid  = (size_t)blockIdx.x * 256 + threadIdx.x;
    const size_t base = gid << 3;                    // element index (8/thread)
    const int b = (int)(base >> 20);
    const int i = (int)(base >> 10) & (N - 1);
    const int j = (int)base & (N - 1);

    const uint4 u = __ldcs(reinterpret_cast<const uint4*>(
        g_e + ((size_t)b << 20) + ((size_t)i << 10) + j));
    const float2 e0 = __half22float2(*reinterpret_cast<const __half2*>(&u.x));
    const float2 e1 = __half22float2(*reinterpret_cast<const __half2*>(&u.y));
    const float2 e2 = __half22float2(*reinterpret_cast<const __half2*>(&u.z));
    const float2 e3 = __half22float2(*reinterpret_cast<const __half2*>(&u.w));

    const float r = __ldg(&g_R[(b << 10) + i]);
    const float4 ca = *reinterpret_cast<const float4*>(&g_C[(b << 10) + j]);
    const float4 cb = *reinterpret_cast<const float4*>(&g_C[(b << 10) + j + 4]);

    float4 oa, ob;
    oa.x = e0.x * __expf(-r - ca.x);
    oa.y = e0.y * __expf(-r - ca.y);
    oa.z = e1.x * __expf(-r - ca.z);
    oa.w = e1.y * __expf(-r - ca.w);
    ob.x = e2.x * __expf(-r - cb.x);
    ob.y = e2.y * __expf(-r - cb.y);
    ob.z = e3.x * __expf(-r - cb.z);
    ob.w = e3.y * __expf(-r - cb.w);
    __stcs(o4 + (gid << 1), oa);
    __stcs(o4 + (gid << 1) + 1, ob);
}

// ---------------------------------------------------------------------------
extern "C" void kernel_launch(void* const* d_in, const int* in_sizes, int n_in,
                              void* d_out, int out_size) {
    const float* s = (const float*)d_in[0];
    float* out = (float*)d_out;

    const dim3 fgrid(RBLKS, BATCH);
    const int fin_blocks = BATCH * N / 2 / 256;       // 128
    const int out_blocks = (BATCH * N * N / 8) / 256; // 8 elems per thread

    pass0<<<fgrid, 256>>>(s);                 // iters 0+1, builds exp cache
    finalize_col<true><<<fin_blocks, 256>>>();
    pass_h<<<fgrid, 256>>>();                 // iters 2+3
    finalize_col<false><<<fin_blocks, 256>>>();
    pass_h<<<fgrid, 256>>>();                 // iters 4+5
    finalize_col<false><<<fin_blocks, 256>>>();
    pass_h<<<fgrid, 256>>>();                 // iters 6+7
    finalize_col<false><<<fin_blocks, 256>>>();
    pass_h<<<fgrid, 256>>>();                 // iters 8+9
    finalize_col<false><<<fin_blocks, 256>>>();

    out_pass<<<out_blocks, 256>>>((float4*)out);
}

// round 16
// speedup vs baseline: 1.0772x; 1.0608x over previous
#include <cuda_runtime.h>
#include <cuda_fp16.h>
#include <cstdint>

#define BATCH 64
#define N 1024
#define RBLKS 32            // row-blocks per batch (32 rows each)

// Scratch (W-representation: W = exp(-C), Rinv = exp(-R); no logs anywhere)
__device__ float  g_Rinv[BATCH * N];                // final pass only
__device__ float  g_W[BATCH * N];
__device__ __half g_parth[BATCH * RBLKS * N];       // 4 MB half partials
__device__ __half g_e[(size_t)BATCH * N * N];       // 128 MB: exp(s) in fp16

// ---------------------------------------------------------------------------
// Pass 0 (iters 0+1): reads fp32 s ONCE, writes e = exp(s) as half,
// rinv_i = 1/sum_j exp(s_ij), col partials S_j += exp(s_ij)*rinv_i.
// Warp-per-row, 4 rows/warp. grid = (RBLKS, BATCH), block = 256.
// ---------------------------------------------------------------------------
__global__ void __launch_bounds__(256) pass0(const float* __restrict__ s) {
    __shared__ __half2 stage[8][N / 2];   // 16 KB
    const int b    = blockIdx.y;
    const int tid  = threadIdx.x;
    const int warp = tid >> 5;
    const int lane = tid & 31;

    __half2 cacc[16];
    #pragma unroll
    for (int k = 0; k < 16; k++) cacc[k] = __float2half2_rn(0.f);

    #pragma unroll 1
    for (int g = 0; g < 4; g++) {
        const int row = (blockIdx.x << 5) + (g << 3) + warp;
        const float*  p  = s   + ((size_t)b << 20) + ((size_t)row << 10);
        __half*       ep = g_e + ((size_t)b << 20) + ((size_t)row << 10);

        __half2 eh[16];
        float sum = 0.f;
        #pragma unroll
        for (int k = 0; k < 8; k++) {
            const int j = (lane << 2) + (k << 7);
            const float4 sv = __ldcs(reinterpret_cast<const float4*>(p + j));
            const float ex = __expf(sv.x), ey = __expf(sv.y);
            const float ez = __expf(sv.z), ew = __expf(sv.w);
            const __half2 h0 = __floats2half2_rn(ex, ey);
            const __half2 h1 = __floats2half2_rn(ez, ew);
            eh[2*k+0] = h0; eh[2*k+1] = h1;
            uint2 u;
            u.x = *reinterpret_cast<const unsigned int*>(&h0);
            u.y = *reinterpret_cast<const unsigned int*>(&h1);
            __stcs(reinterpret_cast<uint2*>(ep + j), u);
            sum += (ex + ey) + (ez + ew);
        }
        #pragma unroll
        for (int off = 16; off; off >>= 1)
            sum += __shfl_xor_sync(0xffffffffu, sum, off);

        const __half2 rin = __float2half2_rn(__fdividef(1.f, sum));
        #pragma unroll
        for (int k = 0; k < 16; k++) cacc[k] = __hfma2(eh[k], rin, cacc[k]);
    }

    #pragma unroll
    for (int k = 0; k < 8; k++) {
        const int jh = (lane << 1) + (k << 6);
        stage[warp][jh]     = cacc[2*k+0];
        stage[warp][jh + 1] = cacc[2*k+1];
    }
    __syncthreads();
    float a0 = 0.f, a1 = 0.f, a2 = 0.f, a3 = 0.f;
    #pragma unroll
    for (int w = 0; w < 8; w++) {
        const float2 f0 = __half22float2(stage[w][(tid << 1)]);
        const float2 f1 = __half22float2(stage[w][(tid << 1) + 1]);
        a0 += f0.x; a1 += f0.y; a2 += f1.x; a3 += f1.y;
    }
    const __half2 h0 = __floats2half2_rn(a0, a1);
    const __half2 h1 = __floats2half2_rn(a2, a3);
    uint2 u;
    u.x = *reinterpret_cast<const unsigned int*>(&h0);
    u.y = *reinterpret_cast<const unsigned int*>(&h1);
    reinterpret_cast<uint2*>(
        g_parth + ((size_t)(b * RBLKS + blockIdx.x)) * N)[tid] = u;
}

// ---------------------------------------------------------------------------
// Half pass (one iter pair), W-representation, half2-native:
//   sum_i = sum_j e_ij * W_j     (W preloaded as half2 smem)
//   partials S_j += e_ij * W_j * rinv_i
// Tail is shfl-reduce + MUFU rcp + HFMA2 only (no logf, no expf).
// LAST: also stores g_Rinv[row] = 1/sum for the output pass.
// grid = (RBLKS, BATCH), block = 256, warp-per-row, 4 rows/warp.
// ---------------------------------------------------------------------------
template <bool LAST>
__global__ void __launch_bounds__(256) pass_h() {
    __shared__ __half2 w2_s[N / 2];       // 1 KB
    __shared__ __half2 stage[8][N / 2];   // 16 KB
    const int b    = blockIdx.y;
    const int tid  = threadIdx.x;
    const int warp = tid >> 5;
    const int lane = tid & 31;

    {   // prologue: load W (fp32) -> half2 smem (no exp needed)
        const float4 c = *reinterpret_cast<const float4*>(&g_W[b * N + (tid << 2)]);
        w2_s[(tid << 1)]     = __floats2half2_rn(c.x, c.y);
        w2_s[(tid << 1) + 1] = __floats2half2_rn(c.z, c.w);
    }
    __syncthreads();

    __half2 cacc[16];
    #pragma unroll
    for (int k = 0; k < 16; k++) cacc[k] = __float2half2_rn(0.f);

    #pragma unroll 1
    for (int g = 0; g < 4; g++) {
        const int row = (blockIdx.x << 5) + (g << 3) + warp;
        const __half2* ep2 = reinterpret_cast<const __half2*>(
            g_e + ((size_t)b << 20) + ((size_t)row << 10));

        __half2 ph[16];
        float sum = 0.f;
        #pragma unroll
        for (int k = 0; k < 4; k++) {
            const int jh = (lane << 2) + (k << 7);
            const uint4 u  = __ldcs(reinterpret_cast<const uint4*>(ep2 + jh));
            const uint4 wv = *reinterpret_cast<const uint4*>(&w2_s[jh]);
            const __half2 p0 = __hmul2(*reinterpret_cast<const __half2*>(&u.x),
                                       *reinterpret_cast<const __half2*>(&wv.x));
            const __half2 p1 = __hmul2(*reinterpret_cast<const __half2*>(&u.y),
                                       *reinterpret_cast<const __half2*>(&wv.y));
            const __half2 p2 = __hmul2(*reinterpret_cast<const __half2*>(&u.z),
                                       *reinterpret_cast<const __half2*>(&wv.z));
            const __half2 p3 = __hmul2(*reinterpret_cast<const __half2*>(&u.w),
                                       *reinterpret_cast<const __half2*>(&wv.w));
            ph[4*k+0] = p0; ph[4*k+1] = p1; ph[4*k+2] = p2; ph[4*k+3] = p3;
            const __half2 t = __hadd2(__hadd2(p0, p1), __hadd2(p2, p3));
            const float2 tf = __half22float2(t);
            sum += tf.x + tf.y;
        }
        #pragma unroll
        for (int off = 16; off; off >>= 1)
            sum += __shfl_xor_sync(0xffffffffu, sum, off);

        const float rscal = __fdividef(1.f, sum);
        if (LAST && lane == 0) g_Rinv[b * N + row] = rscal;
        const __half2 rin = __float2half2_rn(rscal);
        #pragma unroll
        for (int k = 0; k < 16; k++) cacc[k] = __hfma2(ph[k], rin, cacc[k]);
    }

    // cross-warp reduce of column partials (cols j = 2*(lane*4+k*128)+m)
    #pragma unroll
    for (int k = 0; k < 4; k++) {
        const int jh = (lane << 2) + (k << 7);
        #pragma unroll
        for (int m = 0; m < 4; m++) stage[warp][jh + m] = cacc[4*k + m];
    }
    __syncthreads();
    float a0 = 0.f, a1 = 0.f, a2 = 0.f, a3 = 0.f;
    #pragma unroll
    for (int w = 0; w < 8; w++) {
        const float2 f0 = __half22float2(stage[w][(tid << 1)]);
        const float2 f1 = __half22float2(stage[w][(tid << 1) + 1]);
        a0 += f0.x; a1 += f0.y; a2 += f1.x; a3 += f1.y;
    }
    const __half2 h0 = __floats2half2_rn(a0, a1);
    const __half2 h1 = __floats2half2_rn(a2, a3);
    uint2 u;
    u.x = *reinterpret_cast<const unsigned int*>(&h0);
    u.y = *reinterpret_cast<const unsigned int*>(&h1);
    reinterpret_cast<uint2*>(
        g_parth + ((size_t)(b * RBLKS + blockIdx.x)) * N)[tid] = u;
}

// ---------------------------------------------------------------------------
// Finalize: S_j = sum_r part[r][j];  W = 1/S (FIRST) or W = W/S.
// FIRST never reads g_W -> replay-safe. No logs. grid = 128 CTAs.
// ---------------------------------------------------------------------------
template <bool FIRST>
__global__ void __launch_bounds__(256) finalize_col() {
    const int q  = blockIdx.x * 256 + threadIdx.x;   // half2 index: b*512 + jh
    const int b  = q >> 9;
    const int jh = q & 511;
    float sx = 0.f, sy = 0.f;
    #pragma unroll
    for (int r = 0; r < RBLKS; r++) {
        const __half2 v = *reinterpret_cast<const __half2*>(
            g_parth + ((size_t)(b * RBLKS + r)) * N + (jh << 1));
        const float2 f = __half22float2(v);
        sx += f.x; sy += f.y;
    }
    float2* w2 = reinterpret_cast<float2*>(&g_W[b * N + (jh << 1)]);
    if (FIRST) {
        *w2 = make_float2(__fdividef(1.f, sx), __fdividef(1.f, sy));
    } else {
        const float2 w = *w2;
        *w2 = make_float2(__fdividef(w.x, sx), __fdividef(w.y, sy));
    }
}

// ---------------------------------------------------------------------------
// Output pass: out = e_half * Rinv[b][i] * W[b][j] — pure multiplies,
// zero transcendentals. Reads the 128 MB half exp-cache, 8 elems/thread.
// ---------------------------------------------------------------------------
__global__ void __launch_bounds__(256) out_pass(float4* __restrict__ o4) {
    const size_t gid  = (size_t)blockIdx.x * 256 + threadIdx.x;
    const size_t base = gid << 3;                    // element index (8/thread)
    const int b = (int)(base >> 20);
    const int i = (int)(base >> 10) & (N - 1);
    const int j = (int)base & (N - 1);

    const uint4 u = __ldcs(reinterpret_cast<const uint4*>(
        g_e + ((size_t)b << 20) + ((size_t)i << 10) + j));
    const float2 e0 = __half22float2(*reinterpret_cast<const __half2*>(&u.x));
    const float2 e1 = __half22float2(*reinterpret_cast<const __half2*>(&u.y));
    const float2 e2 = __half22float2(*reinterpret_cast<const __half2*>(&u.z));
    const float2 e3 = __half22float2(*reinterpret_cast<const __half2*>(&u.w));

    const float r = __ldg(&g_Rinv[(b << 10) + i]);
    const float4 wa = *reinterpret_cast<const float4*>(&g_W[(b << 10) + j]);
    const float4 wb = *reinterpret_cast<const float4*>(&g_W[(b << 10) + j + 4]);

    float4 oa, ob;
    oa.x = e0.x * r * wa.x;
    oa.y = e0.y * r * wa.y;
    oa.z = e1.x * r * wa.z;
    oa.w = e1.y * r * wa.w;
    ob.x = e2.x * r * wb.x;
    ob.y = e2.y * r * wb.y;
    ob.z = e3.x * r * wb.z;
    ob.w = e3.y * r * wb.w;
    __stcs(o4 + (gid << 1), oa);
    __stcs(o4 + (gid << 1) + 1, ob);
}

// ---------------------------------------------------------------------------
extern "C" void kernel_launch(void* const* d_in, const int* in_sizes, int n_in,
                              void* d_out, int out_size) {
    const float* s = (const float*)d_in[0];
    float* out = (float*)d_out;

    const dim3 fgrid(RBLKS, BATCH);
    const int fin_blocks = BATCH * N / 2 / 256;       // 128
    const int out_blocks = (BATCH * N * N / 8) / 256; // 8 elems per thread

    pass0<<<fgrid, 256>>>(s);                 // iters 0+1, builds exp cache
    finalize_col<true><<<fin_blocks, 256>>>();
    pass_h<false><<<fgrid, 256>>>();          // iters 2+3
    finalize_col<false><<<fin_blocks, 256>>>();
    pass_h<false><<<fgrid, 256>>>();          // iters 4+5
    finalize_col<false><<<fin_blocks, 256>>>();
    pass_h<false><<<fgrid, 256>>>();          // iters 6+7
    finalize_col<false><<<fin_blocks, 256>>>();
    pass_h<true><<<fgrid, 256>>>();           // iters 8+9 (stores Rinv)
    finalize_col<false><<<fin_blocks, 256>>>();

    out_pass<<<out_blocks, 256>>>((float4*)out);
}

// round 17
// speedup vs baseline: 1.0972x; 1.0186x over previous
#include <cuda_runtime.h>
#include <cuda_fp16.h>
#include <cstdint>

#define BATCH 64
#define N 1024
#define RBLKS 32            // row-blocks per batch (32 rows each)

// Scratch (W-representation: W = exp(-C), Rinv = exp(-R); no logs anywhere)
__device__ float  g_Rinv[BATCH * N];                // final pass only
__device__ float  g_W[BATCH * N];
__device__ __half g_parth[BATCH * RBLKS * N];       // 4 MB half partials
__device__ __half g_e[(size_t)BATCH * N * N];       // 128 MB: exp(s) in fp16

// ---------------------------------------------------------------------------
// Pass 0 (iters 0+1): reads fp32 s ONCE, writes e = exp(s) as half,
// rinv_i = 1/sum_j exp(s_ij), col partials S_j += exp(s_ij)*rinv_i.
// Warp-per-row, 4 rows/warp. grid = (RBLKS, BATCH), block = 256.
// ---------------------------------------------------------------------------
__global__ void __launch_bounds__(256) pass0(const float* __restrict__ s) {
    __shared__ __half2 stage[8][N / 2];   // 16 KB
    const int b    = blockIdx.y;
    const int tid  = threadIdx.x;
    const int warp = tid >> 5;
    const int lane = tid & 31;

    __half2 cacc[16];
    #pragma unroll
    for (int k = 0; k < 16; k++) cacc[k] = __float2half2_rn(0.f);

    #pragma unroll 1
    for (int g = 0; g < 4; g++) {
        const int row = (blockIdx.x << 5) + (g << 3) + warp;
        const float*  p  = s   + ((size_t)b << 20) + ((size_t)row << 10);
        __half*       ep = g_e + ((size_t)b << 20) + ((size_t)row << 10);

        __half2 eh[16];
        float sum = 0.f;
        #pragma unroll
        for (int k = 0; k < 8; k++) {
            const int j = (lane << 2) + (k << 7);
            const float4 sv = __ldcs(reinterpret_cast<const float4*>(p + j));
            const float ex = __expf(sv.x), ey = __expf(sv.y);
            const float ez = __expf(sv.z), ew = __expf(sv.w);
            const __half2 h0 = __floats2half2_rn(ex, ey);
            const __half2 h1 = __floats2half2_rn(ez, ew);
            eh[2*k+0] = h0; eh[2*k+1] = h1;
            uint2 u;
            u.x = *reinterpret_cast<const unsigned int*>(&h0);
            u.y = *reinterpret_cast<const unsigned int*>(&h1);
            __stcs(reinterpret_cast<uint2*>(ep + j), u);
            sum += (ex + ey) + (ez + ew);
        }
        #pragma unroll
        for (int off = 16; off; off >>= 1)
            sum += __shfl_xor_sync(0xffffffffu, sum, off);

        const __half2 rin = __float2half2_rn(__fdividef(1.f, sum));
        #pragma unroll
        for (int k = 0; k < 16; k++) cacc[k] = __hfma2(eh[k], rin, cacc[k]);
    }

    #pragma unroll
    for (int k = 0; k < 8; k++) {
        const int jh = (lane << 1) + (k << 6);
        stage[warp][jh]     = cacc[2*k+0];
        stage[warp][jh + 1] = cacc[2*k+1];
    }
    __syncthreads();
    float a0 = 0.f, a1 = 0.f, a2 = 0.f, a3 = 0.f;
    #pragma unroll
    for (int w = 0; w < 8; w++) {
        const float2 f0 = __half22float2(stage[w][(tid << 1)]);
        const float2 f1 = __half22float2(stage[w][(tid << 1) + 1]);
        a0 += f0.x; a1 += f0.y; a2 += f1.x; a3 += f1.y;
    }
    const __half2 h0 = __floats2half2_rn(a0, a1);
    const __half2 h1 = __floats2half2_rn(a2, a3);
    uint2 u;
    u.x = *reinterpret_cast<const unsigned int*>(&h0);
    u.y = *reinterpret_cast<const unsigned int*>(&h1);
    reinterpret_cast<uint2*>(
        g_parth + ((size_t)(b * RBLKS + blockIdx.x)) * N)[tid] = u;
}

// ---------------------------------------------------------------------------
// Half pass (one iter pair), W-representation, half2-native:
//   sum_i = sum_j e_ij * W_j     (W preloaded as half2 smem)
//   partials S_j += e_ij * W_j * rinv_i
// Tail is shfl-reduce + MUFU rcp + HFMA2 only (no logf, no expf).
// LAST: also stores g_Rinv[row] = 1/sum for the output pass.
// grid = (RBLKS, BATCH), block = 256, warp-per-row, 4 rows/warp.
// ---------------------------------------------------------------------------
template <bool LAST>
__global__ void __launch_bounds__(256) pass_h() {
    __shared__ __half2 w2_s[N / 2];       // 1 KB
    __shared__ __half2 stage[8][N / 2];   // 16 KB
    const int b    = blockIdx.y;
    const int tid  = threadIdx.x;
    const int warp = tid >> 5;
    const int lane = tid & 31;

    {   // prologue: load W (fp32) -> half2 smem (no exp needed)
        const float4 c = *reinterpret_cast<const float4*>(&g_W[b * N + (tid << 2)]);
        w2_s[(tid << 1)]     = __floats2half2_rn(c.x, c.y);
        w2_s[(tid << 1) + 1] = __floats2half2_rn(c.z, c.w);
    }
    __syncthreads();

    __half2 cacc[16];
    #pragma unroll
    for (int k = 0; k < 16; k++) cacc[k] = __float2half2_rn(0.f);

    #pragma unroll 1
    for (int g = 0; g < 4; g++) {
        const int row = (blockIdx.x << 5) + (g << 3) + warp;
        const __half2* ep2 = reinterpret_cast<const __half2*>(
            g_e + ((size_t)b << 20) + ((size_t)row << 10));

        __half2 ph[16];
        float sum = 0.f;
        #pragma unroll
        for (int k = 0; k < 4; k++) {
            const int jh = (lane << 2) + (k << 7);
            const uint4 u  = __ldcs(reinterpret_cast<const uint4*>(ep2 + jh));
            const uint4 wv = *reinterpret_cast<const uint4*>(&w2_s[jh]);
            const __half2 p0 = __hmul2(*reinterpret_cast<const __half2*>(&u.x),
                                       *reinterpret_cast<const __half2*>(&wv.x));
            const __half2 p1 = __hmul2(*reinterpret_cast<const __half2*>(&u.y),
                                       *reinterpret_cast<const __half2*>(&wv.y));
            const __half2 p2 = __hmul2(*reinterpret_cast<const __half2*>(&u.z),
                                       *reinterpret_cast<const __half2*>(&wv.z));
            const __half2 p3 = __hmul2(*reinterpret_cast<const __half2*>(&u.w),
                                       *reinterpret_cast<const __half2*>(&wv.w));
            ph[4*k+0] = p0; ph[4*k+1] = p1; ph[4*k+2] = p2; ph[4*k+3] = p3;
            const __half2 t = __hadd2(__hadd2(p0, p1), __hadd2(p2, p3));
            const float2 tf = __half22float2(t);
            sum += tf.x + tf.y;
        }
        #pragma unroll
        for (int off = 16; off; off >>= 1)
            sum += __shfl_xor_sync(0xffffffffu, sum, off);

        const float rscal = __fdividef(1.f, sum);
        if (LAST && lane == 0) g_Rinv[b * N + row] = rscal;
        const __half2 rin = __float2half2_rn(rscal);
        #pragma unroll
        for (int k = 0; k < 16; k++) cacc[k] = __hfma2(ph[k], rin, cacc[k]);
    }

    // cross-warp reduce of column partials (cols j = 2*(lane*4+k*128)+m)
    #pragma unroll
    for (int k = 0; k < 4; k++) {
        const int jh = (lane << 2) + (k << 7);
        #pragma unroll
        for (int m = 0; m < 4; m++) stage[warp][jh + m] = cacc[4*k + m];
    }
    __syncthreads();
    float a0 = 0.f, a1 = 0.f, a2 = 0.f, a3 = 0.f;
    #pragma unroll
    for (int w = 0; w < 8; w++) {
        const float2 f0 = __half22float2(stage[w][(tid << 1)]);
        const float2 f1 = __half22float2(stage[w][(tid << 1) + 1]);
        a0 += f0.x; a1 += f0.y; a2 += f1.x; a3 += f1.y;
    }
    const __half2 h0 = __floats2half2_rn(a0, a1);
    const __half2 h1 = __floats2half2_rn(a2, a3);
    uint2 u;
    u.x = *reinterpret_cast<const unsigned int*>(&h0);
    u.y = *reinterpret_cast<const unsigned int*>(&h1);
    reinterpret_cast<uint2*>(
        g_parth + ((size_t)(b * RBLKS + blockIdx.x)) * N)[tid] = u;
}

// ---------------------------------------------------------------------------
// Finalize v2: S_j = sum_r part[r][j];  W = 1/S (FIRST) or W = W/S.
// Two threads per half2 column (each sums 16 of 32 partials; one smem
// combine) -> 65536 threads across 256 CTAs instead of 32768/128: finalize
// was latency-starved at 0.86 CTA/SM (DRAM 10.5%). Coalescing unchanged
// (consecutive c -> consecutive half2). FIRST never reads g_W -> replay-safe.
// grid = BATCH*4 = 256 CTAs, 256 threads.
// ---------------------------------------------------------------------------
template <bool FIRST>
__global__ void __launch_bounds__(256) finalize_col() {
    __shared__ float2 red[128];
    const int b  = blockIdx.x >> 2;
    const int cg = blockIdx.x & 3;            // column group (128 half2 each)
    const int c  = threadIdx.x & 127;
    const int h  = threadIdx.x >> 7;          // 0 or 1: which 16 partials
    const int jh = (cg << 7) + c;

    float sx = 0.f, sy = 0.f;
    #pragma unroll
    for (int r = 0; r < 16; r++) {
        const __half2 v = *reinterpret_cast<const __half2*>(
            g_parth + ((size_t)(b * RBLKS + (h << 4) + r)) * N + (jh << 1));
        const float2 f = __half22float2(v);
        sx += f.x; sy += f.y;
    }
    if (h == 1) red[c] = make_float2(sx, sy);
    __syncthreads();
    if (h == 0) {
        sx += red[c].x; sy += red[c].y;
        float2* w2 = reinterpret_cast<float2*>(&g_W[b * N + (jh << 1)]);
        if (FIRST) {
            *w2 = make_float2(__fdividef(1.f, sx), __fdividef(1.f, sy));
        } else {
            const float2 w = *w2;
            *w2 = make_float2(__fdividef(w.x, sx), __fdividef(w.y, sy));
        }
    }
}

// ---------------------------------------------------------------------------
// Output pass: out = e_half * Rinv[b][i] * W[b][j] — pure multiplies,
// zero transcendentals. Reads the 128 MB half exp-cache, 8 elems/thread.
// ---------------------------------------------------------------------------
__global__ void __launch_bounds__(256) out_pass(float4* __restrict__ o4) {
    const size_t gid  = (size_t)blockIdx.x * 256 + threadIdx.x;
    const size_t base = gid << 3;                    // element index (8/thread)
    const int b = (int)(base >> 20);
    const int i = (int)(base >> 10) & (N - 1);
    const int j = (int)base & (N - 1);

    const uint4 u = __ldcs(reinterpret_cast<const uint4*>(
        g_e + ((size_t)b << 20) + ((size_t)i << 10) + j));
    const float2 e0 = __half22float2(*reinterpret_cast<const __half2*>(&u.x));
    const float2 e1 = __half22float2(*reinterpret_cast<const __half2*>(&u.y));
    const float2 e2 = __half22float2(*reinterpret_cast<const __half2*>(&u.z));
    const float2 e3 = __half22float2(*reinterpret_cast<const __half2*>(&u.w));

    const float r = __ldg(&g_Rinv[(b << 10) + i]);
    const float4 wa = *reinterpret_cast<const float4*>(&g_W[(b << 10) + j]);
    const float4 wb = *reinterpret_cast<const float4*>(&g_W[(b << 10) + j + 4]);

    float4 oa, ob;
    oa.x = e0.x * r * wa.x;
    oa.y = e0.y * r * wa.y;
    oa.z = e1.x * r * wa.z;
    oa.w = e1.y * r * wa.w;
    ob.x = e2.x * r * wb.x;
    ob.y = e2.y * r * wb.y;
    ob.z = e3.x * r * wb.z;
    ob.w = e3.y * r * wb.w;
    __stcs(o4 + (gid << 1), oa);
    __stcs(o4 + (gid << 1) + 1, ob);
}

// ---------------------------------------------------------------------------
extern "C" void kernel_launch(void* const* d_in, const int* in_sizes, int n_in,
                              void* d_out, int out_size) {
    const float* s = (const float*)d_in[0];
    float* out = (float*)d_out;

    const dim3 fgrid(RBLKS, BATCH);
    const int fin_blocks = BATCH * 4;                 // 256
    const int out_blocks = (BATCH * N * N / 8) / 256; // 8 elems per thread

    pass0<<<fgrid, 256>>>(s);                 // iters 0+1, builds exp cache
    finalize_col<true><<<fin_blocks, 256>>>();
    pass_h<false><<<fgrid, 256>>>();          // iters 2+3
    finalize_col<false><<<fin_blocks, 256>>>();
    pass_h<false><<<fgrid, 256>>>();          // iters 4+5
    finalize_col<false><<<fin_blocks, 256>>>();
    pass_h<false><<<fgrid, 256>>>();          // iters 6+7
    finalize_col<false><<<fin_blocks, 256>>>();
    pass_h<true><<<fgrid, 256>>>();           // iters 8+9 (stores Rinv)
    finalize_col<false><<<fin_blocks, 256>>>();

    out_pass<<<out_blocks, 256>>>((float4*)out);
}